// round 6
// baseline (speedup 1.0000x reference)
#include <cuda_runtime.h>
#include <cstdint>

#define RR 100
#define BB 8
#define IWW 64
#define DD 128
#define BDD 32
#define OWW 16
#define NTILES (RR * RR)
#define KB_GRID 444          // 3 CTAs/SM * 148 SMs, single wave
#define KB_THREADS 160       // 4 consumer warps + 1 producer warp
#define STAGE_BYTES 16384    // 32 rows * 512 B

typedef unsigned long long ull;

// ---- packed fp32x2 helpers (sm_103a FFMA2 path, PTX-only) ----
__device__ __forceinline__ ull pk2(float lo, float hi) {
    ull r; asm("mov.b64 %0,{%1,%2};" : "=l"(r) : "f"(lo), "f"(hi)); return r;
}
__device__ __forceinline__ void upk2(float& lo, float& hi, ull v) {
    asm("mov.b64 {%0,%1},%2;" : "=f"(lo), "=f"(hi) : "l"(v));
}
__device__ __forceinline__ ull fma2(ull a, ull b, ull c) {
    ull d; asm("fma.rn.f32x2 %0,%1,%2,%3;" : "=l"(d) : "l"(a), "l"(b), "l"(c)); return d;
}
__device__ __forceinline__ ull add2(ull a, ull b) {
    ull d; asm("add.rn.f32x2 %0,%1,%2;" : "=l"(d) : "l"(a), "l"(b)); return d;
}

// ---- mbarrier / bulk-async helpers ----
__device__ __forceinline__ uint32_t smem_u32(const void* p) {
    return (uint32_t)__cvta_generic_to_shared(p);
}
__device__ __forceinline__ void mbar_init(uint32_t a, uint32_t cnt) {
    asm volatile("mbarrier.init.shared.b64 [%0], %1;" :: "r"(a), "r"(cnt) : "memory");
}
__device__ __forceinline__ void mbar_arrive(uint32_t a) {
    asm volatile("mbarrier.arrive.shared.b64 _, [%0];" :: "r"(a) : "memory");
}
__device__ __forceinline__ void mbar_expect_tx(uint32_t a, uint32_t bytes) {
    asm volatile("mbarrier.arrive.expect_tx.shared.b64 _, [%0], %1;"
                 :: "r"(a), "r"(bytes) : "memory");
}
__device__ __forceinline__ void mbar_wait(uint32_t a, uint32_t phase) {
    asm volatile(
        "{\n\t.reg .pred P;\n"
        "LW%=:\n\t"
        "mbarrier.try_wait.parity.acquire.cta.shared::cta.b64 P, [%0], %1;\n\t"
        "@P bra LD%=;\n\t"
        "bra LW%=;\n"
        "LD%=:\n\t}"
        :: "r"(a), "r"(phase) : "memory");
}
__device__ __forceinline__ void bulk_cp(uint32_t dst, const void* src,
                                        uint32_t bytes, uint32_t mbar) {
    asm volatile(
        "cp.async.bulk.shared::cta.global.mbarrier::complete_tx::bytes [%0], [%1], %2, [%3];"
        :: "r"(dst), "l"(src), "r"(bytes), "r"(mbar) : "memory");
}
__device__ __forceinline__ void barc128() {   // named barrier: 128 consumer threads
    asm volatile("bar.sync 1, 128;" ::: "memory");
}

// Scratch (allocation-free rule: __device__ globals)
__device__ float g_q[BB * RR * DD];     // [b][r][d]
__device__ float g_K[BB * RR * DD];     // [b][r][d]
__device__ float g_Vn[BB * RR * BDD];   // [b][r][bd]
__device__ float g_attn[BB * RR * RR];  // [b][s][t]  (relu'd raw logits)

// Packed linear stage with 16-deep load batching.
template<int N>
__device__ __forceinline__ void lin2(ull acc2[2], const float* __restrict__ W,
                                     int ldw, const ull x2[][2]) {
    #pragma unroll
    for (int base = 0; base < N; base += 16) {
        float wb[16];
        #pragma unroll
        for (int u = 0; u < 16; u++) wb[u] = __ldg(W + (size_t)(base + u) * ldw);
        #pragma unroll
        for (int u = 0; u < 16; u++) {
            ull w2 = pk2(wb[u], wb[u]);
            acc2[0] = fma2(x2[base + u][0], w2, acc2[0]);
            acc2[1] = fma2(x2[base + u][1], w2, acc2[1]);
        }
    }
}

// ---------------------------------------------------------------------------
// Kernel A: per-region embeddings. grid = (R, 3 paths, 2 batch-halves).
// ---------------------------------------------------------------------------
__global__ __launch_bounds__(128) void kA(
    const float* __restrict__ x, const float* __restrict__ mean,
    const float* __restrict__ stddev,
    const float* __restrict__ kv_in_W, const float* __restrict__ kv_in_b,
    const float* __restrict__ kv_blk_W, const float* __restrict__ kv_blk_b,
    const float* __restrict__ q_in_W, const float* __restrict__ q_in_b,
    const float* __restrict__ q_blk_W, const float* __restrict__ q_blk_b,
    const float* __restrict__ key_W, const float* __restrict__ key_b,
    const float* __restrict__ value_W, const float* __restrict__ value_b)
{
    int r = blockIdx.x;
    int path = blockIdx.y;
    int bh = blockIdx.z;
    int d = threadIdx.x;

    __shared__ ull xn2[IWW][2];
    __shared__ ull h2[DD][2];
    __shared__ float kvs[4][DD];

    float mu = mean[r];
    float isd = 1.0f / (stddev[r] + 1e-8f);
    {
        int i = d & 63, p = d >> 6;
        int b0 = 4 * bh + 2 * p;
        float a = (x[(b0 * RR + r) * IWW + i] - mu) * isd;
        float bb = (x[((b0 + 1) * RR + r) * IWW + i] - mu) * isd;
        xn2[i][p] = pk2(a, bb);
    }
    __syncthreads();

    ull acc2[2];

    if (path == 0) {
        {
            float bi = q_in_b[r * DD + d];
            acc2[0] = acc2[1] = pk2(bi, bi);
            lin2<IWW>(acc2, q_in_W + (size_t)r * IWW * DD + d, DD, xn2);
            #pragma unroll
            for (int p = 0; p < 2; p++) {
                float lo, hi; upk2(lo, hi, acc2[p]);
                h2[d][p] = pk2(fmaxf(lo, 0.0f), fmaxf(hi, 0.0f));
            }
            __syncthreads();
        }
        {
            float bi = q_blk_b[r * DD + d];
            acc2[0] = acc2[1] = pk2(bi, bi);
            lin2<DD>(acc2, q_blk_W + (size_t)r * DD * DD + d, DD, h2);
            #pragma unroll
            for (int p = 0; p < 2; p++) {
                float lo, hi; upk2(lo, hi, acc2[p]);
                int b0 = 4 * bh + 2 * p;
                g_q[(b0 * RR + r) * DD + d] = lo;
                g_q[((b0 + 1) * RR + r) * DD + d] = hi;
            }
        }
        return;
    }

    {
        float bi = kv_in_b[d];
        acc2[0] = acc2[1] = pk2(bi, bi);
        lin2<IWW>(acc2, kv_in_W + d, DD, xn2);
        #pragma unroll
        for (int p = 0; p < 2; p++) {
            float lo, hi; upk2(lo, hi, acc2[p]);
            h2[d][p] = pk2(fmaxf(lo, 0.0f), fmaxf(hi, 0.0f));
        }
        __syncthreads();
    }
    {
        float bi = kv_blk_b[d];
        acc2[0] = acc2[1] = pk2(bi, bi);
        lin2<DD>(acc2, kv_blk_W + d, DD, h2);
        __syncthreads();
        #pragma unroll
        for (int p = 0; p < 2; p++) {
            float lo, hi; upk2(lo, hi, acc2[p]);
            h2[d][p] = pk2(lo, hi);
            if (path == 2) { kvs[2 * p][d] = lo; kvs[2 * p + 1][d] = hi; }
        }
        __syncthreads();
    }

    if (path == 1) {
        float bi = key_b[d];
        acc2[0] = acc2[1] = pk2(bi, bi);
        lin2<DD>(acc2, key_W + d, DD, h2);
        #pragma unroll
        for (int p = 0; p < 2; p++) {
            float lo, hi; upk2(lo, hi, acc2[p]);
            int b0 = 4 * bh + 2 * p;
            g_K[(b0 * RR + r) * DD + d] = lo;
            g_K[((b0 + 1) * RR + r) * DD + d] = hi;
        }
    } else {
        int w = d >> 5, lane = d & 31;
        float v = value_b[lane];
        const float* W = value_W + lane;
        #pragma unroll
        for (int base = 0; base < DD; base += 16) {
            float wb[16];
            #pragma unroll
            for (int u = 0; u < 16; u++) wb[u] = __ldg(W + (size_t)(base + u) * BDD);
            #pragma unroll
            for (int u = 0; u < 16; u++) v = fmaf(kvs[w][base + u], wb[u], v);
        }
        float ss = v * v;
        #pragma unroll
        for (int o = 16; o > 0; o >>= 1) ss += __shfl_xor_sync(0xffffffffu, ss, o);
        int b = 4 * bh + w;
        g_Vn[(b * RR + r) * BDD + lane] = v / fmaxf(sqrtf(ss), 1e-12f);
    }
}

// ---------------------------------------------------------------------------
// Kernel B: persistent producer/consumer. 444 CTAs, 160 threads.
// Producer warp (warp 4, lane 0) streams 16KB stages of query_weight tiles
// into a 4-slot smem ring via cp.async.bulk. Consumer warps 0-3 compute
// rows [32w, 32w+32) of each tile from smem. Per-slot full/empty mbarriers;
// phase = local iteration parity.
// ---------------------------------------------------------------------------
__global__ __launch_bounds__(KB_THREADS) void kB(
    const float* __restrict__ qw, const float* __restrict__ qb)
{
    extern __shared__ __align__(1024) char smem[];
    float* stage = (float*)smem;                                 // 4 * 16384 B
    ull (*q2)[4] = (ull(*)[4])(smem + 4 * STAGE_BYTES);          // 4096 B
    ull (*k2)[4] = (ull(*)[4])(smem + 4 * STAGE_BYTES + 4096);   // 4096 B
    float* sred = (float*)(smem + 4 * STAGE_BYTES + 8192);       // 4*8*4 = 128 B
    ull* bars = (ull*)(smem + 4 * STAGE_BYTES + 8192 + 128);     // 8 mbarriers

    int tid = threadIdx.x;
    int w = tid >> 5, lane = tid & 31;

    uint32_t full_b[4], empty_b[4];
    #pragma unroll
    for (int st = 0; st < 4; st++) {
        full_b[st]  = smem_u32(&bars[st]);
        empty_b[st] = smem_u32(&bars[4 + st]);
    }

    if (tid == 0) {
        #pragma unroll
        for (int st = 0; st < 4; st++) {
            mbar_init(full_b[st], 1);    // producer's expect_tx arrive
            mbar_init(empty_b[st], 1);   // consumer warp's single-lane arrive
        }
    }
    __syncthreads();

    if (w == 4) {
        // ---------------- producer ----------------
        if (lane == 0) {
            int it = 0;
            for (int tile = blockIdx.x; tile < NTILES; tile += KB_GRID, it++) {
                const float* base = qw + (size_t)tile * (DD * DD);
                uint32_t ph = (uint32_t)(it & 1);
                #pragma unroll
                for (int st = 0; st < 4; st++) {
                    mbar_wait(empty_b[st], ph);
                    mbar_expect_tx(full_b[st], STAGE_BYTES);
                    bulk_cp(smem_u32(stage + st * (STAGE_BYTES / 4)),
                            base + st * (STAGE_BYTES / 4), STAGE_BYTES, full_b[st]);
                }
            }
        }
        return;
    }

    // ---------------- consumers (warps 0-3, 128 threads) ----------------
    // initial "empty" arrivals so the producer's first waits pass
    if (lane == 0) mbar_arrive(empty_b[w]);

    int dbase = 4 * lane;
    int it = 0;
    for (int tile = blockIdx.x; tile < NTILES; tile += KB_GRID, it++) {
        int s = tile / RR, t = tile % RR;
        uint32_t ph = (uint32_t)(it & 1);

        // pack q (region s) and K (region t) cooperatively
        {
            int d = tid;
            float qv[BB], kv[BB];
            #pragma unroll
            for (int b = 0; b < BB; b++) {
                qv[b] = g_q[(b * RR + s) * DD + d];
                kv[b] = g_K[(b * RR + t) * DD + d];
            }
            #pragma unroll
            for (int p = 0; p < 4; p++) {
                q2[d][p] = pk2(qv[2 * p], qv[2 * p + 1]);
                k2[d][p] = pk2(kv[2 * p], kv[2 * p + 1]);
            }
        }
        barc128();

        // wait for this warp's stage, then compute its 32 rows from smem
        mbar_wait(full_b[w], ph);

        ull acc2[4][4];
        #pragma unroll
        for (int c = 0; c < 4; c++)
            #pragma unroll
            for (int p = 0; p < 4; p++) acc2[c][p] = 0ull;

        const float4* Ws = reinterpret_cast<const float4*>(
            stage + w * (STAGE_BYTES / 4)) + lane;
        #pragma unroll 8
        for (int u = 0; u < 32; u++) {
            float4 wv = Ws[u * 32];                 // row u, lane's 16 B
            int i = w * 32 + u;
            ulonglong2 qA = *reinterpret_cast<const ulonglong2*>(&q2[i][0]);
            ulonglong2 qB = *reinterpret_cast<const ulonglong2*>(&q2[i][2]);
            ull w0 = pk2(wv.x, wv.x);
            ull w1 = pk2(wv.y, wv.y);
            ull w2_ = pk2(wv.z, wv.z);
            ull w3 = pk2(wv.w, wv.w);
            acc2[0][0] = fma2(qA.x, w0, acc2[0][0]);
            acc2[0][1] = fma2(qA.y, w0, acc2[0][1]);
            acc2[0][2] = fma2(qB.x, w0, acc2[0][2]);
            acc2[0][3] = fma2(qB.y, w0, acc2[0][3]);
            acc2[1][0] = fma2(qA.x, w1, acc2[1][0]);
            acc2[1][1] = fma2(qA.y, w1, acc2[1][1]);
            acc2[1][2] = fma2(qB.x, w1, acc2[1][2]);
            acc2[1][3] = fma2(qB.y, w1, acc2[1][3]);
            acc2[2][0] = fma2(qA.x, w2_, acc2[2][0]);
            acc2[2][1] = fma2(qA.y, w2_, acc2[2][1]);
            acc2[2][2] = fma2(qB.x, w2_, acc2[2][2]);
            acc2[2][3] = fma2(qB.y, w2_, acc2[2][3]);
            acc2[3][0] = fma2(qA.x, w3, acc2[3][0]);
            acc2[3][1] = fma2(qA.y, w3, acc2[3][1]);
            acc2[3][2] = fma2(qB.x, w3, acc2[3][2]);
            acc2[3][3] = fma2(qB.y, w3, acc2[3][3]);
        }
        // stage consumed (values live in registers) -> free the slot
        if (lane == 0) mbar_arrive(empty_b[w]);

        // tail: + bias (warp 0 only), dot with K, warp-reduce, stage partials
        ull pp[4];
        #pragma unroll
        for (int p = 0; p < 4; p++) pp[p] = 0ull;
        float4 b4 = __ldg(reinterpret_cast<const float4*>(
            qb + (size_t)tile * DD + dbase));
        float bias[4] = {b4.x, b4.y, b4.z, b4.w};
        #pragma unroll
        for (int c = 0; c < 4; c++) {
            int dd = dbase + c;
            #pragma unroll
            for (int p = 0; p < 4; p++) {
                ull a = acc2[c][p];
                if (w == 0) a = add2(a, pk2(bias[c], bias[c]));
                pp[p] = fma2(a, k2[dd][p], pp[p]);
            }
        }
        float pf[BB];
        #pragma unroll
        for (int p = 0; p < 4; p++) upk2(pf[2 * p], pf[2 * p + 1], pp[p]);
        #pragma unroll
        for (int b = 0; b < BB; b++) {
            #pragma unroll
            for (int o = 16; o > 0; o >>= 1)
                pf[b] += __shfl_xor_sync(0xffffffffu, pf[b], o);
        }
        if (lane == 0) {
            #pragma unroll
            for (int b = 0; b < BB; b++) sred[w * BB + b] = pf[b];
        }
        barc128();   // sred ready; also protects q2/k2 reuse next iter
        if (tid < BB) {
            float l = sred[0 * BB + tid] + sred[1 * BB + tid] +
                      sred[2 * BB + tid] + sred[3 * BB + tid];
            g_attn[(tid * RR + s) * RR + t] = fmaxf(l, 0.0f);
        }
    }
}

// ---------------------------------------------------------------------------
// Kernel C: normalize attn, attn@Vn, reproj, post block, out proj, denorm.
// ---------------------------------------------------------------------------
__global__ __launch_bounds__(128) void kC(
    const float* __restrict__ reproj_W, const float* __restrict__ reproj_b,
    const float* __restrict__ post_blk_W, const float* __restrict__ post_blk_b,
    const float* __restrict__ out_W, const float* __restrict__ out_b,
    const float* __restrict__ mean, const float* __restrict__ stddev,
    float* __restrict__ out)
{
    int s = blockIdx.x;
    int tid = threadIdx.x;

    __shared__ float at[BB][RR];
    __shared__ float ao[BB][BDD];
    __shared__ __align__(16) ull ar2[DD][4];
    __shared__ float hs[BB][DD];
    __shared__ float inv[BB];

    for (int idx = tid; idx < BB * RR; idx += 128) {
        int b = idx / RR, t = idx % RR;
        at[b][t] = g_attn[(b * RR + s) * RR + t];
    }
    __syncthreads();
    if (tid < BB) {
        float sum = 0.0f;
        #pragma unroll 10
        for (int t = 0; t < RR; t++) sum += at[tid][t];
        inv[tid] = 1.0f / (1e-8f + sum);
    }
    __syncthreads();

    {
        int bd = tid & 31;
        int bh = tid >> 5;
        int b0 = bh, b1 = bh + 4;
        float a0 = 0.0f, a1 = 0.0f;
        const float* V0 = g_Vn + (size_t)(b0 * RR) * BDD + bd;
        const float* V1 = g_Vn + (size_t)(b1 * RR) * BDD + bd;
        #pragma unroll 10
        for (int t = 0; t < RR; t++) {
            a0 = fmaf(at[b0][t], V0[(size_t)t * BDD], a0);
            a1 = fmaf(at[b1][t], V1[(size_t)t * BDD], a1);
        }
        ao[b0][bd] = a0 * inv[b0];
        ao[b1][bd] = a1 * inv[b1];
    }
    __syncthreads();

    int d = tid;
    {
        float rb = reproj_b[d];
        float acc[BB];
        #pragma unroll
        for (int b = 0; b < BB; b++) acc[b] = rb;
        const float* W = reproj_W + d;
        #pragma unroll
        for (int base = 0; base < BDD; base += 16) {
            float wb[16];
            #pragma unroll
            for (int u = 0; u < 16; u++) wb[u] = __ldg(W + (size_t)(base + u) * DD);
            #pragma unroll
            for (int u = 0; u < 16; u++)
                #pragma unroll
                for (int b = 0; b < BB; b++) acc[b] = fmaf(ao[b][base + u], wb[u], acc[b]);
        }
        #pragma unroll
        for (int p = 0; p < 4; p++)
            ar2[d][p] = pk2(fmaxf(acc[2 * p], 0.0f), fmaxf(acc[2 * p + 1], 0.0f));
        __syncthreads();
    }
    {
        float pb = post_blk_b[s * DD + d];
        ull acc2[4];
        #pragma unroll
        for (int p = 0; p < 4; p++) acc2[p] = pk2(pb, pb);
        const float* W = post_blk_W + (size_t)s * DD * DD + d;
        #pragma unroll
        for (int base = 0; base < DD; base += 16) {
            float wb[16];
            #pragma unroll
            for (int u = 0; u < 16; u++) wb[u] = __ldg(W + (size_t)(base + u) * DD);
            #pragma unroll
            for (int u = 0; u < 16; u++) {
                ull w2 = pk2(wb[u], wb[u]);
                ulonglong2 aA = *reinterpret_cast<const ulonglong2*>(&ar2[base + u][0]);
                ulonglong2 aB = *reinterpret_cast<const ulonglong2*>(&ar2[base + u][2]);
                acc2[0] = fma2(aA.x, w2, acc2[0]);
                acc2[1] = fma2(aA.y, w2, acc2[1]);
                acc2[2] = fma2(aB.x, w2, acc2[2]);
                acc2[3] = fma2(aB.y, w2, acc2[3]);
            }
        }
        #pragma unroll
        for (int p = 0; p < 4; p++) {
            float lo, hi; upk2(lo, hi, acc2[p]);
            hs[2 * p][d] = lo; hs[2 * p + 1][d] = hi;
        }
        __syncthreads();
    }
    {
        int b = tid >> 4, o = tid & 15;
        float p = out_b[s * OWW + o];
        const float* W = out_W + (size_t)s * DD * OWW + o;
        #pragma unroll
        for (int base = 0; base < DD; base += 16) {
            float wb[16];
            #pragma unroll
            for (int u = 0; u < 16; u++) wb[u] = __ldg(W + (size_t)(base + u) * OWW);
            #pragma unroll
            for (int u = 0; u < 16; u++) p = fmaf(hs[b][base + u], wb[u], p);
        }
        out[(b * RR + s) * OWW + o] = p * stddev[s] + mean[s];
    }
}

extern "C" void kernel_launch(void* const* d_in, const int* in_sizes, int n_in,
                              void* d_out, int out_size)
{
    const float* x          = (const float*)d_in[0];
    const float* mean       = (const float*)d_in[1];
    const float* stddev     = (const float*)d_in[2];
    const float* kv_in_W    = (const float*)d_in[3];
    const float* kv_in_b    = (const float*)d_in[4];
    const float* kv_blk_W   = (const float*)d_in[5];
    const float* kv_blk_b   = (const float*)d_in[6];
    const float* q_in_W     = (const float*)d_in[7];
    const float* q_in_b     = (const float*)d_in[8];
    const float* q_blk_W    = (const float*)d_in[9];
    const float* q_blk_b    = (const float*)d_in[10];
    const float* key_W      = (const float*)d_in[11];
    const float* key_b      = (const float*)d_in[12];
    const float* value_W    = (const float*)d_in[13];
    const float* value_b    = (const float*)d_in[14];
    const float* qw         = (const float*)d_in[15];
    const float* qb         = (const float*)d_in[16];
    const float* reproj_W   = (const float*)d_in[17];
    const float* reproj_b   = (const float*)d_in[18];
    const float* post_blk_W = (const float*)d_in[19];
    const float* post_blk_b = (const float*)d_in[20];
    const float* out_W      = (const float*)d_in[21];
    const float* out_b      = (const float*)d_in[22];
    float* out = (float*)d_out;

    // 4 stages + q2 + k2 + sred + 8 mbarriers
    int kb_smem = 4 * STAGE_BYTES + 4096 + 4096 + 128 + 64;
    static int attr_done = 0;
    if (!attr_done) {
        cudaFuncSetAttribute(kB, cudaFuncAttributeMaxDynamicSharedMemorySize, kb_smem);
        attr_done = 1;
    }

    kA<<<dim3(RR, 3, 2), 128>>>(x, mean, stddev, kv_in_W, kv_in_b, kv_blk_W, kv_blk_b,
                                q_in_W, q_in_b, q_blk_W, q_blk_b,
                                key_W, key_b, value_W, value_b);
    kB<<<KB_GRID, KB_THREADS, kb_smem>>>(qw, qb);
    kC<<<RR, 128>>>(reproj_W, reproj_b, post_blk_W, post_blk_b,
                    out_W, out_b, mean, stddev, out);
}

// round 7
// speedup vs baseline: 1.1695x; 1.1695x over previous
#include <cuda_runtime.h>
#include <cstdint>

#define RR 100
#define BB 8
#define IWW 64
#define DD 128
#define BDD 32
#define OWW 16

typedef unsigned long long ull;

// ---- packed fp32x2 helpers (sm_103a FFMA2 path, PTX-only) ----
__device__ __forceinline__ ull pk2(float lo, float hi) {
    ull r; asm("mov.b64 %0,{%1,%2};" : "=l"(r) : "f"(lo), "f"(hi)); return r;
}
__device__ __forceinline__ void upk2(float& lo, float& hi, ull v) {
    asm("mov.b64 {%0,%1},%2;" : "=f"(lo), "=f"(hi) : "l"(v));
}
__device__ __forceinline__ ull fma2(ull a, ull b, ull c) {
    ull d; asm("fma.rn.f32x2 %0,%1,%2,%3;" : "=l"(d) : "l"(a), "l"(b), "l"(c)); return d;
}
__device__ __forceinline__ ull add2(ull a, ull b) {
    ull d; asm("add.rn.f32x2 %0,%1,%2;" : "=l"(d) : "l"(a), "l"(b)); return d;
}

// Scratch (allocation-free rule: __device__ globals)
__device__ float g_q[BB * RR * DD];     // [b][r][d]
__device__ float g_K[BB * RR * DD];     // [b][r][d]
__device__ float g_Vn[BB * RR * BDD];   // [b][r][bd]
__device__ float g_attn[BB * RR * RR];  // [b][s][t]  (relu'd raw logits)

// Packed linear stage with 32-deep load batching (32 LDGs in flight).
template<int N>
__device__ __forceinline__ void lin2(ull acc2[2], const float* __restrict__ W,
                                     int ldw, const ull x2[][2]) {
    #pragma unroll
    for (int base = 0; base < N; base += 32) {
        float wb[32];
        #pragma unroll
        for (int u = 0; u < 32; u++) wb[u] = __ldg(W + (size_t)(base + u) * ldw);
        #pragma unroll
        for (int u = 0; u < 32; u++) {
            ull w2 = pk2(wb[u], wb[u]);
            acc2[0] = fma2(x2[base + u][0], w2, acc2[0]);
            acc2[1] = fma2(x2[base + u][1], w2, acc2[1]);
        }
    }
}

// ---------------------------------------------------------------------------
// Kernel A: per-region embeddings. grid = (R, 3 paths, 2 batch-halves).
// ---------------------------------------------------------------------------
__global__ __launch_bounds__(128) void kA(
    const float* __restrict__ x, const float* __restrict__ mean,
    const float* __restrict__ stddev,
    const float* __restrict__ kv_in_W, const float* __restrict__ kv_in_b,
    const float* __restrict__ kv_blk_W, const float* __restrict__ kv_blk_b,
    const float* __restrict__ q_in_W, const float* __restrict__ q_in_b,
    const float* __restrict__ q_blk_W, const float* __restrict__ q_blk_b,
    const float* __restrict__ key_W, const float* __restrict__ key_b,
    const float* __restrict__ value_W, const float* __restrict__ value_b)
{
    int r = blockIdx.x;
    int path = blockIdx.y;
    int bh = blockIdx.z;          // batch half: batches [4*bh, 4*bh+4)
    int d = threadIdx.x;

    __shared__ ull xn2[IWW][2];
    __shared__ ull h2[DD][2];
    __shared__ float kvs[4][DD];

    float mu = mean[r];
    float isd = 1.0f / (stddev[r] + 1e-8f);
    {
        int i = d & 63, p = d >> 6;
        int b0 = 4 * bh + 2 * p;
        float a = (x[(b0 * RR + r) * IWW + i] - mu) * isd;
        float bb = (x[((b0 + 1) * RR + r) * IWW + i] - mu) * isd;
        xn2[i][p] = pk2(a, bb);
    }
    __syncthreads();

    ull acc2[2];

    if (path == 0) {
        {
            float bi = q_in_b[r * DD + d];
            acc2[0] = acc2[1] = pk2(bi, bi);
            lin2<IWW>(acc2, q_in_W + (size_t)r * IWW * DD + d, DD, xn2);
            #pragma unroll
            for (int p = 0; p < 2; p++) {
                float lo, hi; upk2(lo, hi, acc2[p]);
                h2[d][p] = pk2(fmaxf(lo, 0.0f), fmaxf(hi, 0.0f));
            }
            __syncthreads();
        }
        {
            float bi = q_blk_b[r * DD + d];
            acc2[0] = acc2[1] = pk2(bi, bi);
            lin2<DD>(acc2, q_blk_W + (size_t)r * DD * DD + d, DD, h2);
            #pragma unroll
            for (int p = 0; p < 2; p++) {
                float lo, hi; upk2(lo, hi, acc2[p]);
                int b0 = 4 * bh + 2 * p;
                g_q[(b0 * RR + r) * DD + d] = lo;
                g_q[((b0 + 1) * RR + r) * DD + d] = hi;
            }
        }
        return;
    }

    {
        float bi = kv_in_b[d];
        acc2[0] = acc2[1] = pk2(bi, bi);
        lin2<IWW>(acc2, kv_in_W + d, DD, xn2);
        #pragma unroll
        for (int p = 0; p < 2; p++) {
            float lo, hi; upk2(lo, hi, acc2[p]);
            h2[d][p] = pk2(fmaxf(lo, 0.0f), fmaxf(hi, 0.0f));
        }
        __syncthreads();
    }
    {
        float bi = kv_blk_b[d];
        acc2[0] = acc2[1] = pk2(bi, bi);
        lin2<DD>(acc2, kv_blk_W + d, DD, h2);
        __syncthreads();
        #pragma unroll
        for (int p = 0; p < 2; p++) {
            float lo, hi; upk2(lo, hi, acc2[p]);
            h2[d][p] = pk2(lo, hi);
            if (path == 2) { kvs[2 * p][d] = lo; kvs[2 * p + 1][d] = hi; }
        }
        __syncthreads();
    }

    if (path == 1) {
        float bi = key_b[d];
        acc2[0] = acc2[1] = pk2(bi, bi);
        lin2<DD>(acc2, key_W + d, DD, h2);
        #pragma unroll
        for (int p = 0; p < 2; p++) {
            float lo, hi; upk2(lo, hi, acc2[p]);
            int b0 = 4 * bh + 2 * p;
            g_K[(b0 * RR + r) * DD + d] = lo;
            g_K[((b0 + 1) * RR + r) * DD + d] = hi;
        }
    } else {
        int w = d >> 5, lane = d & 31;
        float v = value_b[lane];
        const float* W = value_W + lane;
        #pragma unroll
        for (int base = 0; base < DD; base += 32) {
            float wb[32];
            #pragma unroll
            for (int u = 0; u < 32; u++) wb[u] = __ldg(W + (size_t)(base + u) * BDD);
            #pragma unroll
            for (int u = 0; u < 32; u++) v = fmaf(kvs[w][base + u], wb[u], v);
        }
        float ss = v * v;
        #pragma unroll
        for (int o = 16; o > 0; o >>= 1) ss += __shfl_xor_sync(0xffffffffu, ss, o);
        int b = 4 * bh + w;
        g_Vn[(b * RR + r) * BDD + lane] = v / fmaxf(sqrtf(ss), 1e-12f);
    }
}

// ---------------------------------------------------------------------------
// Kernel B: attention logits (round-4 proven version). One CTA per (s,t);
// streams the 64KB W tile with LDG.128 (thread owns 4 d-columns; warp owns a
// 32-row range). Partials dotted with K immediately; cross-warp smem reduce.
// ---------------------------------------------------------------------------
__global__ __launch_bounds__(128) void kB(
    const float* __restrict__ qw, const float* __restrict__ qb)
{
    int t = blockIdx.x;
    int s = blockIdx.y;
    int tid = threadIdx.x;
    int w = tid >> 5, lane = tid & 31;
    int dbase = 4 * lane;

    __shared__ __align__(16) ull q2[DD][4];  // [i][pair]: (b=2p, b=2p+1)
    __shared__ __align__(16) ull k2[DD][4];
    __shared__ float sred[4][BB];

    {
        int d = tid;
        float qv[BB], kv[BB];
        #pragma unroll
        for (int b = 0; b < BB; b++) {
            qv[b] = g_q[(b * RR + s) * DD + d];
            kv[b] = g_K[(b * RR + t) * DD + d];
        }
        #pragma unroll
        for (int p = 0; p < 4; p++) {
            q2[d][p] = pk2(qv[2 * p], qv[2 * p + 1]);
            k2[d][p] = pk2(kv[2 * p], kv[2 * p + 1]);
        }
    }
    __syncthreads();

    ull acc2[4][4];
    #pragma unroll
    for (int c = 0; c < 4; c++)
        #pragma unroll
        for (int p = 0; p < 4; p++) acc2[c][p] = 0ull;

    const float* W = qw + ((size_t)(s * RR + t)) * DD * DD + (size_t)w * 32 * DD + dbase;
    #pragma unroll
    for (int ii0 = 0; ii0 < 32; ii0 += 8) {
        float4 wv[8];
        #pragma unroll
        for (int u = 0; u < 8; u++)
            wv[u] = __ldcs(reinterpret_cast<const float4*>(W + (size_t)(ii0 + u) * DD));
        #pragma unroll
        for (int u = 0; u < 8; u++) {
            int i = w * 32 + ii0 + u;
            ulonglong2 qA = *reinterpret_cast<const ulonglong2*>(&q2[i][0]);
            ulonglong2 qB = *reinterpret_cast<const ulonglong2*>(&q2[i][2]);
            ull w0 = pk2(wv[u].x, wv[u].x);
            ull w1 = pk2(wv[u].y, wv[u].y);
            ull w2_ = pk2(wv[u].z, wv[u].z);
            ull w3 = pk2(wv[u].w, wv[u].w);
            acc2[0][0] = fma2(qA.x, w0, acc2[0][0]);
            acc2[0][1] = fma2(qA.y, w0, acc2[0][1]);
            acc2[0][2] = fma2(qB.x, w0, acc2[0][2]);
            acc2[0][3] = fma2(qB.y, w0, acc2[0][3]);
            acc2[1][0] = fma2(qA.x, w1, acc2[1][0]);
            acc2[1][1] = fma2(qA.y, w1, acc2[1][1]);
            acc2[1][2] = fma2(qB.x, w1, acc2[1][2]);
            acc2[1][3] = fma2(qB.y, w1, acc2[1][3]);
            acc2[2][0] = fma2(qA.x, w2_, acc2[2][0]);
            acc2[2][1] = fma2(qA.y, w2_, acc2[2][1]);
            acc2[2][2] = fma2(qB.x, w2_, acc2[2][2]);
            acc2[2][3] = fma2(qB.y, w2_, acc2[2][3]);
            acc2[3][0] = fma2(qA.x, w3, acc2[3][0]);
            acc2[3][1] = fma2(qA.y, w3, acc2[3][1]);
            acc2[3][2] = fma2(qB.x, w3, acc2[3][2]);
            acc2[3][3] = fma2(qB.y, w3, acc2[3][3]);
        }
    }

    ull pp[4];
    #pragma unroll
    for (int p = 0; p < 4; p++) pp[p] = 0ull;
    float4 b4 = __ldcs(reinterpret_cast<const float4*>(
        qb + ((size_t)(s * RR + t)) * DD + dbase));
    float bias[4] = {b4.x, b4.y, b4.z, b4.w};
    #pragma unroll
    for (int c = 0; c < 4; c++) {
        int dd = dbase + c;
        #pragma unroll
        for (int p = 0; p < 4; p++) {
            ull a = acc2[c][p];
            if (w == 0) a = add2(a, pk2(bias[c], bias[c]));
            pp[p] = fma2(a, k2[dd][p], pp[p]);
        }
    }
    float pf[BB];
    #pragma unroll
    for (int p = 0; p < 4; p++) upk2(pf[2 * p], pf[2 * p + 1], pp[p]);
    #pragma unroll
    for (int b = 0; b < BB; b++) {
        #pragma unroll
        for (int o = 16; o > 0; o >>= 1)
            pf[b] += __shfl_xor_sync(0xffffffffu, pf[b], o);
    }
    if (lane == 0) {
        #pragma unroll
        for (int b = 0; b < BB; b++) sred[w][b] = pf[b];
    }
    __syncthreads();
    if (tid < BB) {
        float l = sred[0][tid] + sred[1][tid] + sred[2][tid] + sred[3][tid];
        g_attn[(tid * RR + s) * RR + t] = fmaxf(l, 0.0f);
    }
}

// ---------------------------------------------------------------------------
// Kernel C: normalize attn, attn@Vn, reproj, post block, out proj, denorm.
// grid = (R, 2 batch-halves): 200 CTAs (>1/SM) for latency hiding; each CTA
// handles 4 batches (2 packed pairs).
// ---------------------------------------------------------------------------
__global__ __launch_bounds__(128) void kC(
    const float* __restrict__ reproj_W, const float* __restrict__ reproj_b,
    const float* __restrict__ post_blk_W, const float* __restrict__ post_blk_b,
    const float* __restrict__ out_W, const float* __restrict__ out_b,
    const float* __restrict__ mean, const float* __restrict__ stddev,
    float* __restrict__ out)
{
    int s = blockIdx.x;
    int bh = blockIdx.y;          // batches [4*bh, 4*bh+4)
    int tid = threadIdx.x;

    __shared__ float at[4][RR];
    __shared__ float ao[4][BDD];
    __shared__ __align__(16) ull ar2[DD][2];
    __shared__ float hs[4][DD];
    __shared__ float inv[4];

    for (int idx = tid; idx < 4 * RR; idx += 128) {
        int b = idx / RR, t = idx % RR;
        at[b][t] = g_attn[((4 * bh + b) * RR + s) * RR + t];
    }
    __syncthreads();
    if (tid < 4) {
        float sum = 0.0f;
        #pragma unroll 10
        for (int t = 0; t < RR; t++) sum += at[tid][t];
        inv[tid] = 1.0f / (1e-8f + sum);
    }
    __syncthreads();

    // att_out: 128 threads = 4 local batches x 32 bd
    {
        int bd = tid & 31;
        int lb = tid >> 5;      // 0..3
        int b = 4 * bh + lb;
        float a = 0.0f;
        const float* V = g_Vn + (size_t)(b * RR) * BDD + bd;
        #pragma unroll 10
        for (int t = 0; t < RR; t++)
            a = fmaf(at[lb][t], V[(size_t)t * BDD], a);
        ao[lb][bd] = a * inv[lb];
    }
    __syncthreads();

    int d = tid;
    // reproj (BD->D) + relu, packed result
    {
        float rb = reproj_b[d];
        float acc[4];
        #pragma unroll
        for (int b = 0; b < 4; b++) acc[b] = rb;
        const float* W = reproj_W + d;
        {
            float wb[BDD];
            #pragma unroll
            for (int u = 0; u < BDD; u++) wb[u] = __ldg(W + (size_t)u * DD);
            #pragma unroll
            for (int u = 0; u < BDD; u++)
                #pragma unroll
                for (int b = 0; b < 4; b++) acc[b] = fmaf(ao[b][u], wb[u], acc[b]);
        }
        #pragma unroll
        for (int p = 0; p < 2; p++)
            ar2[d][p] = pk2(fmaxf(acc[2 * p], 0.0f), fmaxf(acc[2 * p + 1], 0.0f));
        __syncthreads();
    }
    // post block (D->D), packed, 32-deep batched loads
    {
        float pb = post_blk_b[s * DD + d];
        ull acc2[2];
        #pragma unroll
        for (int p = 0; p < 2; p++) acc2[p] = pk2(pb, pb);
        const float* W = post_blk_W + (size_t)s * DD * DD + d;
        #pragma unroll
        for (int base = 0; base < DD; base += 32) {
            float wb[32];
            #pragma unroll
            for (int u = 0; u < 32; u++) wb[u] = __ldg(W + (size_t)(base + u) * DD);
            #pragma unroll
            for (int u = 0; u < 32; u++) {
                ull w2 = pk2(wb[u], wb[u]);
                ulonglong2 aA = *reinterpret_cast<const ulonglong2*>(&ar2[base + u][0]);
                acc2[0] = fma2(aA.x, w2, acc2[0]);
                acc2[1] = fma2(aA.y, w2, acc2[1]);
            }
        }
        #pragma unroll
        for (int p = 0; p < 2; p++) {
            float lo, hi; upk2(lo, hi, acc2[p]);
            hs[2 * p][d] = lo; hs[2 * p + 1][d] = hi;
        }
        __syncthreads();
    }
    // output projection (D->OW) + denorm; 64 threads = 4 b x 16 o
    if (tid < 64) {
        int lb = tid >> 4, o = tid & 15;
        int b = 4 * bh + lb;
        float p = out_b[s * OWW + o];
        const float* W = out_W + (size_t)s * DD * OWW + o;
        #pragma unroll
        for (int base = 0; base < DD; base += 32) {
            float wb[32];
            #pragma unroll
            for (int u = 0; u < 32; u++) wb[u] = __ldg(W + (size_t)(base + u) * OWW);
            #pragma unroll
            for (int u = 0; u < 32; u++) p = fmaf(hs[lb][base + u], wb[u], p);
        }
        out[(b * RR + s) * OWW + o] = p * stddev[s] + mean[s];
    }
}

extern "C" void kernel_launch(void* const* d_in, const int* in_sizes, int n_in,
                              void* d_out, int out_size)
{
    const float* x          = (const float*)d_in[0];
    const float* mean       = (const float*)d_in[1];
    const float* stddev     = (const float*)d_in[2];
    const float* kv_in_W    = (const float*)d_in[3];
    const float* kv_in_b    = (const float*)d_in[4];
    const float* kv_blk_W   = (const float*)d_in[5];
    const float* kv_blk_b   = (const float*)d_in[6];
    const float* q_in_W     = (const float*)d_in[7];
    const float* q_in_b     = (const float*)d_in[8];
    const float* q_blk_W    = (const float*)d_in[9];
    const float* q_blk_b    = (const float*)d_in[10];
    const float* key_W      = (const float*)d_in[11];
    const float* key_b      = (const float*)d_in[12];
    const float* value_W    = (const float*)d_in[13];
    const float* value_b    = (const float*)d_in[14];
    const float* qw         = (const float*)d_in[15];
    const float* qb         = (const float*)d_in[16];
    const float* reproj_W   = (const float*)d_in[17];
    const float* reproj_b   = (const float*)d_in[18];
    const float* post_blk_W = (const float*)d_in[19];
    const float* post_blk_b = (const float*)d_in[20];
    const float* out_W      = (const float*)d_in[21];
    const float* out_b      = (const float*)d_in[22];
    float* out = (float*)d_out;

    kA<<<dim3(RR, 3, 2), 128>>>(x, mean, stddev, kv_in_W, kv_in_b, kv_blk_W, kv_blk_b,
                                q_in_W, q_in_b, q_blk_W, q_blk_b,
                                key_W, key_b, value_W, value_b);
    kB<<<dim3(RR, RR), 128>>>(qw, qb);
    kC<<<dim3(RR, 2), 128>>>(reproj_W, reproj_b, post_blk_W, post_blk_b,
                             out_W, out_b, mean, stddev, out);
}